// round 11
// baseline (speedup 1.0000x reference)
#include <cuda_runtime.h>
#include <cuda_fp16.h>

#define NN 50000
#define NE 1600000
#define NG 512
#define DH 128
#define DOUT 64

#define NAGG ((NN + 7) / 8)        // 6250 agg blocks
#define NGEMM ((NN + 127) / 128)   // 391 gemm blocks

// ---------------- scratch (static __device__ — no allocations) ----------------
__device__ int                        g_deg[2][NN];
__device__ float                      g_dinv[2][NN];
__device__ int                        g_off[2][NN];
__device__ int                        g_cur[2][NN];
__device__ int                        g_total[2];
__device__ int                        g_csr[2][NE];
__device__ __align__(16) __half       g_h[2][NN * DH];    // h' = dinv*(X@W), fp16
__device__ __align__(16) __half       g_a16[2][NN * DH];  // activations (fp16)
__device__ __align__(16) __half       g_x16[2][NN * DH];  // converted layer-1 input
__device__ __align__(16) __half       g_wt[3][DH * DH];   // W^T fp16: wt[n*DH+k]
__device__ int                        g_goff[2][NG + 1];
__device__ float                      g_emb[2][NG * DOUT];

// ---------------- graph prep (both branches per launch) ----------------
__global__ void zero_k() {
    int i = blockIdx.x * blockDim.x + threadIdx.x;
    if (i < NN) { g_deg[0][i] = 0; g_deg[1][i] = 0; }
    if (i == 0) { g_total[0] = 0; g_total[1] = 0; }
}

__global__ void count_k(const int* __restrict__ dst0, const int* __restrict__ dst1) {
    int e = blockIdx.x * blockDim.x + threadIdx.x;
    if (e < NE) {
        atomicAdd(&g_deg[0][dst0[e]], 1);
        atomicAdd(&g_deg[1][dst1[e]], 1);
    }
}

// scan-free CSR offsets: warp-aggregated atomic chunk assignment + dinv
__global__ void offs_k() {
    int br = blockIdx.y;
    int i = blockIdx.x * blockDim.x + threadIdx.x;
    int lane = threadIdx.x & 31;
    int d = (i < NN) ? g_deg[br][i] : 0;
    int incl = d;
#pragma unroll
    for (int o = 1; o < 32; o <<= 1) {
        int x = __shfl_up_sync(0xffffffffu, incl, o);
        if (lane >= o) incl += x;
    }
    int wsum = __shfl_sync(0xffffffffu, incl, 31);
    int base = 0;
    if (lane == 31) base = atomicAdd(&g_total[br], wsum);
    base = __shfl_sync(0xffffffffu, base, 31);
    if (i < NN) {
        int p = base + incl - d;
        g_off[br][i] = p;
        g_cur[br][i] = p;
        g_dinv[br][i] = rsqrtf((float)(d + 1));  // +1 self-loop
    }
}

__global__ void fill_k(const int* __restrict__ src0, const int* __restrict__ dst0,
                       const int* __restrict__ src1, const int* __restrict__ dst1) {
    int e = blockIdx.x * blockDim.x + threadIdx.x;
    if (e < NE) {
        int p0 = atomicAdd(&g_cur[0][dst0[e]], 1);
        g_csr[0][p0] = src0[e];
        int p1 = atomicAdd(&g_cur[1][dst1[e]], 1);
        g_csr[1][p1] = src1[e];
    }
}

// graph segment boundaries from the sorted batch arrays
__global__ void gbound_k(const int* __restrict__ b0, const int* __restrict__ b1) {
    int br = blockIdx.y;
    const int* __restrict__ batch = br ? b1 : b0;
    int i = blockIdx.x * blockDim.x + threadIdx.x;
    if (i >= NN) return;
    int bc = batch[i];
    if (i == 0) {
        for (int g = 0; g <= bc; g++) g_goff[br][g] = 0;
    } else {
        int bp = batch[i - 1];
        for (int g = bp + 1; g <= bc; g++) g_goff[br][g] = i;
    }
    if (i == NN - 1) {
        for (int g = bc + 1; g <= NG; g++) g_goff[br][g] = NN;
    }
}

// ---------------- converters ----------------
__global__ void wconv_k(const float* __restrict__ W1, const float* __restrict__ W2,
                        const float* __restrict__ W3) {
    int t = blockIdx.x * blockDim.x + threadIdx.x;  // t = k*DH + n (coalesced read)
    if (t < DH * DH) {
        int k = t >> 7, n = t & 127;
        g_wt[0][n * DH + k] = __float2half(W1[t]);
        g_wt[1][n * DH + k] = __float2half(W2[t]);
        g_wt[2][n * DH + k] = __float2half(W3[t]);
    }
}

__global__ void xconv_k(const float* __restrict__ x0, const float* __restrict__ x1) {
    int br = blockIdx.y;
    const float* __restrict__ x = br ? x1 : x0;
    int i = blockIdx.x * blockDim.x + threadIdx.x;  // over NN*DH/4
    if (i < NN * DH / 4) {
        float4 v = ((const float4*)x)[i];
        union { uint2 u; __half2 h[2]; } pk;
        pk.h[0] = __floats2half2_rn(v.x, v.y);
        pk.h[1] = __floats2half2_rn(v.z, v.w);
        ((uint2*)g_x16[br])[i] = pk.u;
    }
}

// ---------------- GEMM body (mma.sync m16n8k16 fp16->fp32), 256 thr ----------
__device__ __forceinline__ void mma16816(float* c, unsigned a0, unsigned a1,
                                         unsigned a2, unsigned a3,
                                         unsigned b0, unsigned b1) {
    asm volatile(
        "mma.sync.aligned.m16n8k16.row.col.f32.f16.f16.f32 "
        "{%0,%1,%2,%3}, {%4,%5,%6,%7}, {%8,%9}, {%0,%1,%2,%3};"
        : "+f"(c[0]), "+f"(c[1]), "+f"(c[2]), "+f"(c[3])
        : "r"(a0), "r"(a1), "r"(a2), "r"(a3), "r"(b0), "r"(b1));
}

__device__ void gemm_body(int br, int from_a, int wsel, int bx,
                          unsigned* As32, unsigned* Ws32) {
    const __half* __restrict__ A  = from_a ? g_a16[br] : g_x16[br];
    const __half* __restrict__ Wt = g_wt[wsel];

    int row0 = bx * 128;
    int t = threadIdx.x;
    int lane = t & 31;
    int wid = t >> 5;
    int warp_m = wid & 3;
    int warp_n = wid >> 2;
    int g = lane >> 2;
    int tig = lane & 3;

    float c[2][8][4];
#pragma unroll
    for (int mt = 0; mt < 2; mt++)
#pragma unroll
        for (int nt = 0; nt < 8; nt++)
#pragma unroll
            for (int j = 0; j < 4; j++) c[mt][nt][j] = 0.f;

    for (int ks = 0; ks < 2; ks++) {
        __syncthreads();
#pragma unroll
        for (int i = 0; i < 4; i++) {
            int idx = t + i * 256;
            int r = idx >> 3, q = idx & 7;
            uint4 v = make_uint4(0u, 0u, 0u, 0u);
            int gr = row0 + r;
            if (gr < NN) v = *(const uint4*)(A + (size_t)gr * DH + ks * 64 + q * 8);
            *(uint4*)&As32[r * 36 + q * 4] = v;
        }
#pragma unroll
        for (int i = 0; i < 4; i++) {
            int idx = t + i * 256;
            int n = idx >> 3, q = idx & 7;
            uint4 v = *(const uint4*)(Wt + (size_t)n * DH + ks * 64 + q * 8);
            *(uint4*)&Ws32[n * 36 + q * 4] = v;
        }
        __syncthreads();

#pragma unroll
        for (int kc = 0; kc < 4; kc++) {
            unsigned a[2][4];
#pragma unroll
            for (int mt = 0; mt < 2; mt++) {
                int rb = warp_m * 32 + mt * 16;
                a[mt][0] = As32[(rb + g) * 36 + kc * 8 + tig];
                a[mt][1] = As32[(rb + g + 8) * 36 + kc * 8 + tig];
                a[mt][2] = As32[(rb + g) * 36 + kc * 8 + tig + 4];
                a[mt][3] = As32[(rb + g + 8) * 36 + kc * 8 + tig + 4];
            }
#pragma unroll
            for (int nt = 0; nt < 8; nt++) {
                int nb = warp_n * 64 + nt * 8;
                unsigned b0 = Ws32[(nb + g) * 36 + kc * 8 + tig];
                unsigned b1 = Ws32[(nb + g) * 36 + kc * 8 + tig + 4];
                mma16816(c[0][nt], a[0][0], a[0][1], a[0][2], a[0][3], b0, b1);
                mma16816(c[1][nt], a[1][0], a[1][1], a[1][2], a[1][3], b0, b1);
            }
        }
    }

#pragma unroll
    for (int mt = 0; mt < 2; mt++) {
        int r0 = row0 + warp_m * 32 + mt * 16 + g;
        int r1 = r0 + 8;
        float s0 = (r0 < NN) ? g_dinv[br][r0] : 0.f;
        float s1 = (r1 < NN) ? g_dinv[br][r1] : 0.f;
#pragma unroll
        for (int nt = 0; nt < 8; nt++) {
            int col = warp_n * 64 + nt * 8 + 2 * tig;
            float* cc = c[mt][nt];
            if (r0 < NN)
                *(__half2*)(g_h[br] + (size_t)r0 * DH + col) =
                    __floats2half2_rn(s0 * cc[0], s0 * cc[1]);
            if (r1 < NN)
                *(__half2*)(g_h[br] + (size_t)r1 * DH + col) =
                    __floats2half2_rn(s1 * cc[2], s1 * cc[3]);
        }
    }
}

// ---------------- aggregation body: warp-per-node CSR gather (fp16 rows) ------
__device__ void agg_body(int br, const float* __restrict__ bias, int do_relu,
                         int bx) {
    int w = bx * 8 + (threadIdx.x >> 5);
    if (w >= NN) return;
    int lane = threadIdx.x & 31;
    const uint2* __restrict__ Hv = (const uint2*)g_h[br];
    const int* __restrict__ csr = g_csr[br];

    union { uint2 u; __half2 h[2]; } v;
    v.u = __ldg(&Hv[(size_t)w * 32 + lane]);  // self-loop term
    float2 f0 = __half22float2(v.h[0]);
    float2 f1 = __half22float2(v.h[1]);
    float4 acc = make_float4(f0.x, f0.y, f1.x, f1.y);

    int s0 = g_off[br][w];
    int s1 = s0 + g_deg[br][w];
    for (int base = s0; base < s1; base += 32) {
        int e = base + lane;
        int idx = (e < s1) ? __ldg(&csr[e]) : 0;
        int m = min(32, s1 - base);
        int j = 0;
        for (; j + 4 <= m; j += 4) {
            int a0 = __shfl_sync(0xffffffffu, idx, j);
            int a1 = __shfl_sync(0xffffffffu, idx, j + 1);
            int a2 = __shfl_sync(0xffffffffu, idx, j + 2);
            int a3 = __shfl_sync(0xffffffffu, idx, j + 3);
            union { uint2 u; __half2 h[2]; } v0, v1, v2, v3;
            v0.u = __ldg(&Hv[(size_t)a0 * 32 + lane]);
            v1.u = __ldg(&Hv[(size_t)a1 * 32 + lane]);
            v2.u = __ldg(&Hv[(size_t)a2 * 32 + lane]);
            v3.u = __ldg(&Hv[(size_t)a3 * 32 + lane]);
            float2 p0 = __half22float2(v0.h[0]), q0 = __half22float2(v0.h[1]);
            float2 p1 = __half22float2(v1.h[0]), q1 = __half22float2(v1.h[1]);
            float2 p2 = __half22float2(v2.h[0]), q2 = __half22float2(v2.h[1]);
            float2 p3 = __half22float2(v3.h[0]), q3 = __half22float2(v3.h[1]);
            acc.x += (p0.x + p1.x) + (p2.x + p3.x);
            acc.y += (p0.y + p1.y) + (p2.y + p3.y);
            acc.z += (q0.x + q1.x) + (q2.x + q3.x);
            acc.w += (q0.y + q1.y) + (q2.y + q3.y);
        }
        for (; j < m; j++) {
            int a0 = __shfl_sync(0xffffffffu, idx, j);
            union { uint2 u; __half2 h[2]; } v0;
            v0.u = __ldg(&Hv[(size_t)a0 * 32 + lane]);
            float2 p0 = __half22float2(v0.h[0]), q0 = __half22float2(v0.h[1]);
            acc.x += p0.x; acc.y += p0.y; acc.z += q0.x; acc.w += q0.y;
        }
    }
    float di = g_dinv[br][w];
    float4 bb = __ldg(&((const float4*)bias)[lane]);
    float4 o;
    o.x = fmaf(di, acc.x, bb.x);
    o.y = fmaf(di, acc.y, bb.y);
    o.z = fmaf(di, acc.z, bb.z);
    o.w = fmaf(di, acc.w, bb.w);
    if (do_relu) {
        o.x = fmaxf(o.x, 0.f); o.y = fmaxf(o.y, 0.f);
        o.z = fmaxf(o.z, 0.f); o.w = fmaxf(o.w, 0.f);
    }
    union { uint2 u; __half2 h[2]; } pk;
    pk.h[0] = __floats2half2_rn(o.x, o.y);
    pk.h[1] = __floats2half2_rn(o.z, o.w);
    ((uint2*)g_a16[br])[(size_t)w * 32 + lane] = pk.u;
}

// ---------------- standalone gemm (pipeline head) ----------------
__global__ __launch_bounds__(256) void gemm_k(int br, int from_a, int wsel) {
    __shared__ __align__(16) unsigned As32[128 * 36];
    __shared__ __align__(16) unsigned Ws32[128 * 36];
    gemm_body(br, from_a, wsel, blockIdx.x, As32, Ws32);
}

// ---------------- mixed: gemm (blocks [0,NGEMM)) + agg (rest) ----------------
__global__ __launch_bounds__(256) void mixed_ga_k(int gemm_br, int from_a, int wsel,
                                                  int agg_br,
                                                  const float* __restrict__ bias,
                                                  int do_relu) {
    __shared__ __align__(16) unsigned As32[128 * 36];
    __shared__ __align__(16) unsigned Ws32[128 * 36];
    int bx = blockIdx.x;
    if (bx < NGEMM) gemm_body(gemm_br, from_a, wsel, bx, As32, Ws32);
    else            agg_body(agg_br, bias, do_relu, bx - NGEMM);
}

// ---------------- pool body (256-thread block; threads >=128 idle) ------------
__device__ void pool_body(int br, const float* __restrict__ Wlin,
                          const float* __restrict__ blin, int g) {
    __shared__ float m[DH];
    int t = threadIdx.x;
    int s = g_goff[br][g];
    int c = g_goff[br][g + 1] - s;
    if (t < DH) {
        float sum = 0.f;
        for (int r = s; r < s + c; r++)
            sum += __half2float(g_a16[br][(size_t)r * DH + t]);
        m[t] = sum * (1.f / fmaxf((float)c, 1.f));
    }
    __syncthreads();
    if (t < DOUT) {
        float o = blin[t];
#pragma unroll
        for (int f = 0; f < DH; f++) o = fmaf(m[f], Wlin[f * DOUT + t], o);
        g_emb[br][g * DOUT + t] = o;
    }
}

// ---------------- mixed: pool (blocks [0,NG)) + agg (rest) ----------------
__global__ __launch_bounds__(256) void mixed_pa_k(int pool_br,
                                                  const float* __restrict__ Wlin,
                                                  const float* __restrict__ blin,
                                                  int agg_br,
                                                  const float* __restrict__ bias,
                                                  int do_relu) {
    int bx = blockIdx.x;
    if (bx < NG) pool_body(pool_br, Wlin, blin, bx);
    else         agg_body(agg_br, bias, do_relu, bx - NG);
}

// ---------------- standalone pool ----------------
__global__ __launch_bounds__(256) void pool_k(int br, const float* __restrict__ Wlin,
                                              const float* __restrict__ blin) {
    pool_body(br, Wlin, blin, blockIdx.x);
}

// ---------------- pairwise distance ----------------
__global__ void final_k(float* __restrict__ out) {
    int g = blockIdx.x, lane = threadIdx.x;  // 32 threads
    float d0 = g_emb[0][g * DOUT + lane]      - g_emb[1][g * DOUT + lane]      + 1e-6f;
    float d1 = g_emb[0][g * DOUT + lane + 32] - g_emb[1][g * DOUT + lane + 32] + 1e-6f;
    float s = d0 * d0 + d1 * d1;
#pragma unroll
    for (int o = 16; o; o >>= 1) s += __shfl_xor_sync(0xffffffffu, s, o);
    if (lane == 0) out[g] = sqrtf(s);
}

// ---------------- host driver ----------------
extern "C" void kernel_launch(void* const* d_in, const int* in_sizes, int n_in,
                              void* d_out, int out_size) {
    const float* x1 = (const float*)d_in[0];
    const int*   e1 = (const int*)d_in[1];
    const int*   t1 = (const int*)d_in[2];
    const float* x2 = (const float*)d_in[3];
    const int*   e2 = (const int*)d_in[4];
    const int*   t2 = (const int*)d_in[5];
    const float* W1 = (const float*)d_in[6];
    const float* b1 = (const float*)d_in[7];
    const float* W2 = (const float*)d_in[8];
    const float* b2 = (const float*)d_in[9];
    const float* W3 = (const float*)d_in[10];
    const float* b3 = (const float*)d_in[11];
    const float* Wl = (const float*)d_in[12];
    const float* bl = (const float*)d_in[13];

    const int *src1 = e1, *dst1 = e1 + NE;
    const int *src2 = e2, *dst2 = e2 + NE;

    // prep (both branches at once)
    wconv_k<<<(DH * DH + 255) / 256, 256>>>(W1, W2, W3);
    zero_k<<<(NN + 1023) / 1024, 1024>>>();
    count_k<<<(NE + 255) / 256, 256>>>(dst1, dst2);
    offs_k<<<dim3((NN + 255) / 256, 2), 256>>>();
    fill_k<<<(NE + 255) / 256, 256>>>(src1, dst1, src2, dst2);
    gbound_k<<<dim3((NN + 255) / 256, 2), 256>>>(t1, t2);
    xconv_k<<<dim3((NN * DH / 4 + 255) / 256, 2), 256>>>(x1, x2);

    // software pipeline: branch 1 runs one stage behind branch 0, so every
    // tensor-bound GEMM overlaps the other branch's L2-bound aggregation.
    gemm_k<<<NGEMM, 256>>>(0, 0, 0);                               // g(b0,L1)
    mixed_ga_k<<<NGEMM + NAGG, 256>>>(1, 0, 0, /*agg*/0, b1, 1);   // g(b1,L1)+a(b0,L1)
    mixed_ga_k<<<NGEMM + NAGG, 256>>>(0, 1, 1, /*agg*/1, b1, 1);   // g(b0,L2)+a(b1,L1)
    mixed_ga_k<<<NGEMM + NAGG, 256>>>(1, 1, 1, /*agg*/0, b2, 1);   // g(b1,L2)+a(b0,L2)
    mixed_ga_k<<<NGEMM + NAGG, 256>>>(0, 1, 2, /*agg*/1, b2, 1);   // g(b0,L3)+a(b1,L2)
    mixed_ga_k<<<NGEMM + NAGG, 256>>>(1, 1, 2, /*agg*/0, b3, 0);   // g(b1,L3)+a(b0,L3)
    mixed_pa_k<<<NG + NAGG, 256>>>(0, Wl, bl, /*agg*/1, b3, 0);    // p(b0)+a(b1,L3)
    pool_k<<<NG, 256>>>(1, Wl, bl);                                // p(b1)
    final_k<<<NG, 32>>>((float*)d_out);
}

// round 12
// speedup vs baseline: 1.8085x; 1.8085x over previous
#include <cuda_runtime.h>
#include <cuda_fp16.h>

#define NN 50000
#define NE 1600000
#define NG 512
#define DH 128
#define DOUT 64

#define NAGG ((NN + 7) / 8)        // 6250 agg blocks
#define NGEMM ((NN + 127) / 128)   // 391 gemm blocks

// ---------------- scratch (static __device__ — no allocations) ----------------
__device__ int                        g_deg[2][NN];
__device__ float                      g_dinv[2][NN];
__device__ int                        g_off[2][NN];
__device__ int                        g_cur[2][NN];
__device__ int                        g_total[2];
__device__ int                        g_csr[2][NE];
__device__ __align__(16) __half       g_h[2][NN * DH];    // h' = dinv*(X@W), fp16
__device__ __align__(16) __half       g_a16[2][NN * DH];  // activations (fp16)
__device__ __align__(16) __half       g_x16[2][NN * DH];  // converted layer-1 input
__device__ __align__(16) __half       g_wt[3][DH * DH];   // W^T fp16: wt[n*DH+k]
__device__ int                        g_goff[2][NG + 1];
__device__ float                      g_emb[2][NG * DOUT];

// ---------------- graph prep (both branches per launch) ----------------
__global__ void zero_k() {
    int i = blockIdx.x * blockDim.x + threadIdx.x;
    if (i < NN) { g_deg[0][i] = 0; g_deg[1][i] = 0; }
    if (i == 0) { g_total[0] = 0; g_total[1] = 0; }
}

__global__ void count_k(const int* __restrict__ dst0, const int* __restrict__ dst1) {
    int e = blockIdx.x * blockDim.x + threadIdx.x;
    if (e < NE) {
        atomicAdd(&g_deg[0][dst0[e]], 1);
        atomicAdd(&g_deg[1][dst1[e]], 1);
    }
}

// scan-free CSR offsets: warp-aggregated atomic chunk assignment + dinv
__global__ void offs_k() {
    int br = blockIdx.y;
    int i = blockIdx.x * blockDim.x + threadIdx.x;
    int lane = threadIdx.x & 31;
    int d = (i < NN) ? g_deg[br][i] : 0;
    int incl = d;
#pragma unroll
    for (int o = 1; o < 32; o <<= 1) {
        int x = __shfl_up_sync(0xffffffffu, incl, o);
        if (lane >= o) incl += x;
    }
    int wsum = __shfl_sync(0xffffffffu, incl, 31);
    int base = 0;
    if (lane == 31) base = atomicAdd(&g_total[br], wsum);
    base = __shfl_sync(0xffffffffu, base, 31);
    if (i < NN) {
        int p = base + incl - d;
        g_off[br][i] = p;
        g_cur[br][i] = p;
        g_dinv[br][i] = rsqrtf((float)(d + 1));  // +1 self-loop
    }
}

__global__ void fill_k(const int* __restrict__ src0, const int* __restrict__ dst0,
                       const int* __restrict__ src1, const int* __restrict__ dst1) {
    int e = blockIdx.x * blockDim.x + threadIdx.x;
    if (e < NE) {
        int p0 = atomicAdd(&g_cur[0][dst0[e]], 1);
        g_csr[0][p0] = src0[e];
        int p1 = atomicAdd(&g_cur[1][dst1[e]], 1);
        g_csr[1][p1] = src1[e];
    }
}

// graph segment boundaries from the sorted batch arrays
__global__ void gbound_k(const int* __restrict__ b0, const int* __restrict__ b1) {
    int br = blockIdx.y;
    const int* __restrict__ batch = br ? b1 : b0;
    int i = blockIdx.x * blockDim.x + threadIdx.x;
    if (i >= NN) return;
    int bc = batch[i];
    if (i == 0) {
        for (int g = 0; g <= bc; g++) g_goff[br][g] = 0;
    } else {
        int bp = batch[i - 1];
        for (int g = bp + 1; g <= bc; g++) g_goff[br][g] = i;
    }
    if (i == NN - 1) {
        for (int g = bc + 1; g <= NG; g++) g_goff[br][g] = NN;
    }
}

// ---------------- converters ----------------
__global__ void wconv_k(const float* __restrict__ W1, const float* __restrict__ W2,
                        const float* __restrict__ W3) {
    int t = blockIdx.x * blockDim.x + threadIdx.x;  // t = k*DH + n (coalesced read)
    if (t < DH * DH) {
        int k = t >> 7, n = t & 127;
        g_wt[0][n * DH + k] = __float2half(W1[t]);
        g_wt[1][n * DH + k] = __float2half(W2[t]);
        g_wt[2][n * DH + k] = __float2half(W3[t]);
    }
}

__global__ void xconv_k(const float* __restrict__ x0, const float* __restrict__ x1) {
    int br = blockIdx.y;
    const float* __restrict__ x = br ? x1 : x0;
    int i = blockIdx.x * blockDim.x + threadIdx.x;  // over NN*DH/4
    if (i < NN * DH / 4) {
        float4 v = ((const float4*)x)[i];
        union { uint2 u; __half2 h[2]; } pk;
        pk.h[0] = __floats2half2_rn(v.x, v.y);
        pk.h[1] = __floats2half2_rn(v.z, v.w);
        ((uint2*)g_x16[br])[i] = pk.u;
    }
}

// ---------------- GEMM via tensor cores (mma.sync m16n8k16 fp16->fp32) --------
// per-branch launch (1D grid) so branch pipelines can live on separate streams.
__device__ __forceinline__ void mma16816(float* c, unsigned a0, unsigned a1,
                                         unsigned a2, unsigned a3,
                                         unsigned b0, unsigned b1) {
    asm volatile(
        "mma.sync.aligned.m16n8k16.row.col.f32.f16.f16.f32 "
        "{%0,%1,%2,%3}, {%4,%5,%6,%7}, {%8,%9}, {%0,%1,%2,%3};"
        : "+f"(c[0]), "+f"(c[1]), "+f"(c[2]), "+f"(c[3])
        : "r"(a0), "r"(a1), "r"(a2), "r"(a3), "r"(b0), "r"(b1));
}

__global__ __launch_bounds__(256) void gemm_k(int br, int from_a, int wsel) {
    const __half* __restrict__ A  = from_a ? g_a16[br] : g_x16[br];
    const __half* __restrict__ Wt = g_wt[wsel];

    __shared__ __align__(16) unsigned As32[128 * 36];
    __shared__ __align__(16) unsigned Ws32[128 * 36];

    int row0 = blockIdx.x * 128;
    int t = threadIdx.x;
    int lane = t & 31;
    int wid = t >> 5;
    int warp_m = wid & 3;
    int warp_n = wid >> 2;
    int g = lane >> 2;
    int tig = lane & 3;

    float c[2][8][4];
#pragma unroll
    for (int mt = 0; mt < 2; mt++)
#pragma unroll
        for (int nt = 0; nt < 8; nt++)
#pragma unroll
            for (int j = 0; j < 4; j++) c[mt][nt][j] = 0.f;

    for (int ks = 0; ks < 2; ks++) {
        __syncthreads();
#pragma unroll
        for (int i = 0; i < 4; i++) {
            int idx = t + i * 256;
            int r = idx >> 3, q = idx & 7;
            uint4 v = make_uint4(0u, 0u, 0u, 0u);
            int gr = row0 + r;
            if (gr < NN) v = *(const uint4*)(A + (size_t)gr * DH + ks * 64 + q * 8);
            *(uint4*)&As32[r * 36 + q * 4] = v;
        }
#pragma unroll
        for (int i = 0; i < 4; i++) {
            int idx = t + i * 256;
            int n = idx >> 3, q = idx & 7;
            uint4 v = *(const uint4*)(Wt + (size_t)n * DH + ks * 64 + q * 8);
            *(uint4*)&Ws32[n * 36 + q * 4] = v;
        }
        __syncthreads();

#pragma unroll
        for (int kc = 0; kc < 4; kc++) {
            unsigned a[2][4];
#pragma unroll
            for (int mt = 0; mt < 2; mt++) {
                int rb = warp_m * 32 + mt * 16;
                a[mt][0] = As32[(rb + g) * 36 + kc * 8 + tig];
                a[mt][1] = As32[(rb + g + 8) * 36 + kc * 8 + tig];
                a[mt][2] = As32[(rb + g) * 36 + kc * 8 + tig + 4];
                a[mt][3] = As32[(rb + g + 8) * 36 + kc * 8 + tig + 4];
            }
#pragma unroll
            for (int nt = 0; nt < 8; nt++) {
                int nb = warp_n * 64 + nt * 8;
                unsigned b0 = Ws32[(nb + g) * 36 + kc * 8 + tig];
                unsigned b1 = Ws32[(nb + g) * 36 + kc * 8 + tig + 4];
                mma16816(c[0][nt], a[0][0], a[0][1], a[0][2], a[0][3], b0, b1);
                mma16816(c[1][nt], a[1][0], a[1][1], a[1][2], a[1][3], b0, b1);
            }
        }
    }

#pragma unroll
    for (int mt = 0; mt < 2; mt++) {
        int r0 = row0 + warp_m * 32 + mt * 16 + g;
        int r1 = r0 + 8;
        float s0 = (r0 < NN) ? g_dinv[br][r0] : 0.f;
        float s1 = (r1 < NN) ? g_dinv[br][r1] : 0.f;
#pragma unroll
        for (int nt = 0; nt < 8; nt++) {
            int col = warp_n * 64 + nt * 8 + 2 * tig;
            float* cc = c[mt][nt];
            if (r0 < NN)
                *(__half2*)(g_h[br] + (size_t)r0 * DH + col) =
                    __floats2half2_rn(s0 * cc[0], s0 * cc[1]);
            if (r1 < NN)
                *(__half2*)(g_h[br] + (size_t)r1 * DH + col) =
                    __floats2half2_rn(s1 * cc[2], s1 * cc[3]);
        }
    }
}

// ---------------- aggregation: warp-per-node CSR gather-reduce (fp16 rows) -----
__global__ __launch_bounds__(256, 8) void agg_k(int br,
                                                const float* __restrict__ bias,
                                                int do_relu) {
    int w = blockIdx.x * 8 + (threadIdx.x >> 5);
    if (w >= NN) return;
    int lane = threadIdx.x & 31;
    const uint2* __restrict__ Hv = (const uint2*)g_h[br];
    const int* __restrict__ csr = g_csr[br];

    union { uint2 u; __half2 h[2]; } v;
    v.u = __ldg(&Hv[(size_t)w * 32 + lane]);  // self-loop term
    float2 f0 = __half22float2(v.h[0]);
    float2 f1 = __half22float2(v.h[1]);
    float4 acc = make_float4(f0.x, f0.y, f1.x, f1.y);

    int s0 = g_off[br][w];
    int s1 = s0 + g_deg[br][w];
    for (int base = s0; base < s1; base += 32) {
        int e = base + lane;
        int idx = (e < s1) ? __ldg(&csr[e]) : 0;
        int m = min(32, s1 - base);
        int j = 0;
        for (; j + 4 <= m; j += 4) {
            int a0 = __shfl_sync(0xffffffffu, idx, j);
            int a1 = __shfl_sync(0xffffffffu, idx, j + 1);
            int a2 = __shfl_sync(0xffffffffu, idx, j + 2);
            int a3 = __shfl_sync(0xffffffffu, idx, j + 3);
            union { uint2 u; __half2 h[2]; } v0, v1, v2, v3;
            v0.u = __ldg(&Hv[(size_t)a0 * 32 + lane]);
            v1.u = __ldg(&Hv[(size_t)a1 * 32 + lane]);
            v2.u = __ldg(&Hv[(size_t)a2 * 32 + lane]);
            v3.u = __ldg(&Hv[(size_t)a3 * 32 + lane]);
            float2 p0 = __half22float2(v0.h[0]), q0 = __half22float2(v0.h[1]);
            float2 p1 = __half22float2(v1.h[0]), q1 = __half22float2(v1.h[1]);
            float2 p2 = __half22float2(v2.h[0]), q2 = __half22float2(v2.h[1]);
            float2 p3 = __half22float2(v3.h[0]), q3 = __half22float2(v3.h[1]);
            acc.x += (p0.x + p1.x) + (p2.x + p3.x);
            acc.y += (p0.y + p1.y) + (p2.y + p3.y);
            acc.z += (q0.x + q1.x) + (q2.x + q3.x);
            acc.w += (q0.y + q1.y) + (q2.y + q3.y);
        }
        for (; j < m; j++) {
            int a0 = __shfl_sync(0xffffffffu, idx, j);
            union { uint2 u; __half2 h[2]; } v0;
            v0.u = __ldg(&Hv[(size_t)a0 * 32 + lane]);
            float2 p0 = __half22float2(v0.h[0]), q0 = __half22float2(v0.h[1]);
            acc.x += p0.x; acc.y += p0.y; acc.z += q0.x; acc.w += q0.y;
        }
    }
    float di = g_dinv[br][w];
    float4 bb = __ldg(&((const float4*)bias)[lane]);
    float4 o;
    o.x = fmaf(di, acc.x, bb.x);
    o.y = fmaf(di, acc.y, bb.y);
    o.z = fmaf(di, acc.z, bb.z);
    o.w = fmaf(di, acc.w, bb.w);
    if (do_relu) {
        o.x = fmaxf(o.x, 0.f); o.y = fmaxf(o.y, 0.f);
        o.z = fmaxf(o.z, 0.f); o.w = fmaxf(o.w, 0.f);
    }
    union { uint2 u; __half2 h[2]; } pk;
    pk.h[0] = __floats2half2_rn(o.x, o.y);
    pk.h[1] = __floats2half2_rn(o.z, o.w);
    ((uint2*)g_a16[br])[(size_t)w * 32 + lane] = pk.u;
}

// ---------------- fused mean-pool + linear ----------------
__global__ __launch_bounds__(128) void pool_lin_k(int br,
                                                  const float* __restrict__ Wlin,
                                                  const float* __restrict__ blin) {
    int g = blockIdx.x;
    int t = threadIdx.x;  // 128
    int s = g_goff[br][g];
    int c = g_goff[br][g + 1] - s;
    float sum = 0.f;
    for (int r = s; r < s + c; r++) sum += __half2float(g_a16[br][(size_t)r * DH + t]);
    __shared__ float m[DH];
    m[t] = sum * (1.f / fmaxf((float)c, 1.f));
    __syncthreads();
    if (t < DOUT) {
        float o = blin[t];
#pragma unroll
        for (int f = 0; f < DH; f++) o = fmaf(m[f], Wlin[f * DOUT + t], o);
        g_emb[br][g * DOUT + t] = o;
    }
}

// ---------------- pairwise distance ----------------
__global__ void final_k(float* __restrict__ out) {
    int g = blockIdx.x, lane = threadIdx.x;  // 32 threads
    float d0 = g_emb[0][g * DOUT + lane]      - g_emb[1][g * DOUT + lane]      + 1e-6f;
    float d1 = g_emb[0][g * DOUT + lane + 32] - g_emb[1][g * DOUT + lane + 32] + 1e-6f;
    float s = d0 * d0 + d1 * d1;
#pragma unroll
    for (int o = 16; o; o >>= 1) s += __shfl_xor_sync(0xffffffffu, s, o);
    if (lane == 0) out[g] = sqrtf(s);
}

// ---------------- host driver ----------------
extern "C" void kernel_launch(void* const* d_in, const int* in_sizes, int n_in,
                              void* d_out, int out_size) {
    const float* x1 = (const float*)d_in[0];
    const int*   e1 = (const int*)d_in[1];
    const int*   t1 = (const int*)d_in[2];
    const float* x2 = (const float*)d_in[3];
    const int*   e2 = (const int*)d_in[4];
    const int*   t2 = (const int*)d_in[5];
    const float* W1 = (const float*)d_in[6];
    const float* b1 = (const float*)d_in[7];
    const float* W2 = (const float*)d_in[8];
    const float* b2 = (const float*)d_in[9];
    const float* W3 = (const float*)d_in[10];
    const float* b3 = (const float*)d_in[11];
    const float* Wl = (const float*)d_in[12];
    const float* bl = (const float*)d_in[13];

    const int *src1 = e1, *dst1 = e1 + NE;
    const int *src2 = e2, *dst2 = e2 + NE;

    // prep (both branches per launch) on the capture (default) stream
    wconv_k<<<(DH * DH + 255) / 256, 256>>>(W1, W2, W3);
    zero_k<<<(NN + 1023) / 1024, 1024>>>();
    count_k<<<(NE + 255) / 256, 256>>>(dst1, dst2);
    offs_k<<<dim3((NN + 255) / 256, 2), 256>>>();
    fill_k<<<(NE + 255) / 256, 256>>>(src1, dst1, src2, dst2);
    gbound_k<<<dim3((NN + 255) / 256, 2), 256>>>(t1, t2);
    xconv_k<<<dim3((NN * DH / 4 + 255) / 256, 2), 256>>>(x1, x2);

    // fork a second stream so branch pipelines overlap (tensor-bound GEMMs of
    // one branch co-scheduled with L2-bound agg of the other). Standard
    // event-fork/join pattern — capture-legal. Streams/events created per call
    // (kernel_launch runs only a couple of times; no device memory involved).
    cudaStream_t s2;
    cudaStreamCreateWithFlags(&s2, cudaStreamNonBlocking);
    cudaEvent_t evFork, evJoin;
    cudaEventCreateWithFlags(&evFork, cudaEventDisableTiming);
    cudaEventCreateWithFlags(&evJoin, cudaEventDisableTiming);

    cudaEventRecord(evFork, 0);
    cudaStreamWaitEvent(s2, evFork, 0);

    // branch 0 on default stream
    gemm_k<<<NGEMM, 256>>>(0, 0, 0);
    agg_k<<<NAGG, 256>>>(0, b1, 1);
    gemm_k<<<NGEMM, 256>>>(0, 1, 1);
    agg_k<<<NAGG, 256>>>(0, b2, 1);
    gemm_k<<<NGEMM, 256>>>(0, 1, 2);
    agg_k<<<NAGG, 256>>>(0, b3, 0);
    pool_lin_k<<<NG, 128>>>(0, Wl, bl);

    // branch 1 on s2
    gemm_k<<<NGEMM, 256, 0, s2>>>(1, 0, 0);
    agg_k<<<NAGG, 256, 0, s2>>>(1, b1, 1);
    gemm_k<<<NGEMM, 256, 0, s2>>>(1, 1, 1);
    agg_k<<<NAGG, 256, 0, s2>>>(1, b2, 1);
    gemm_k<<<NGEMM, 256, 0, s2>>>(1, 1, 2);
    agg_k<<<NAGG, 256, 0, s2>>>(1, b3, 0);
    pool_lin_k<<<NG, 128, 0, s2>>>(1, Wl, bl);

    cudaEventRecord(evJoin, s2);
    cudaStreamWaitEvent(0, evJoin, 0);

    final_k<<<NG, 32>>>((float*)d_out);
}